// round 16
// baseline (speedup 1.0000x reference)
#include <cuda_runtime.h>
#include <cuda_bf16.h>
#include <limits.h>

// FINAL: single self-sufficient kernel. Block `seg` finds the first/last
// occurrence of its own segment id by scanning the L2-resident mask
// (broadcast across all 512 blocks), then copies the two rows into the
// concatenated output. No global scratch, no global atomics, no inter-kernel
// dependency -> trivially CUDA-graph-replay-safe.
//
// Scan: forward + backward windows processed in the SAME round with all 8
// window loads per thread issued unconditionally (no dependent-load chains);
// block-reduce via shared atomicMin/Max; ONE barrier on the hit path.
// For the bench input both hits land in round 0; the loop keeps the kernel
// correct for arbitrary masks.
//
// Measured design points (GB300 sm_103a, this bench):
//   - 256 thr/block beats 512 (copy is latency/ramp-bound, not issue-bound)
//   - plain __ldg row loads beat __ldcs (evict-first lost coalescing; L2 is
//     not under pressure at an 8.4 MB working set)
//   - __stcs stores help (output is write-once)
//   - fused window-scan beats 2-kernel, PDL-overlap, and grid-barrier forms
//   - wall floor ~6.6 us = ~0.9 replay + ~3.5 ramp/clock floor + ~1.8 work

#define NTHR 256
#define WIN  1024            // ids per window per direction (4 per thread)
#define KPT  (WIN / NTHR)    // 4

__global__ void __launch_bounds__(NTHR) fused_gather_kernel(
        const float* __restrict__ x,
        const int*   __restrict__ mask,
        float*       __restrict__ out,
        int L, int H) {
    const int seg = blockIdx.x;
    const int tid = threadIdx.x;

    __shared__ int s_first, s_last;
    if (tid == 0) { s_first = INT_MAX; s_last = -1; }

    int first = INT_MAX, last = -1;
    int fbase = 0;           // forward window base
    int bend  = L;           // backward window end (exclusive)

    for (;;) {
        // ---- batched, unconditional loads for both windows ----
        int fidx[KPT], fval[KPT], bidx[KPT], bval[KPT];
        bool doF = (first == INT_MAX) && (fbase < L);
        bool doB = (last < 0) && (bend > 0);
        int bstart = bend - WIN > 0 ? bend - WIN : 0;
        #pragma unroll
        for (int k = 0; k < KPT; k++) {
            fidx[k] = fbase + tid + k * NTHR;
            bidx[k] = bstart + tid + k * NTHR;
            fval[k] = (doF && fidx[k] < L)    ? __ldg(mask + fidx[k]) : -1;
            bval[k] = (doB && bidx[k] < bend) ? __ldg(mask + bidx[k]) : -1;
        }
        // ---- local reduce, then block reduce via shared atomics ----
        int lf = INT_MAX, lb = -1;
        #pragma unroll
        for (int k = 0; k < KPT; k++) {
            if (fval[k] == seg && fidx[k] < lf) lf = fidx[k];
            if (bval[k] == seg && bidx[k] > lb) lb = bidx[k];
        }
        if (lf != INT_MAX) atomicMin(&s_first, lf);
        if (lb >= 0)       atomicMax(&s_last, lb);
        __syncthreads();
        first = s_first;
        last  = s_last;
        if (first != INT_MAX && last >= 0) break;   // hit path: 1 barrier
        fbase += WIN;
        bend  = bstart;
        if (fbase >= L && bend <= 0) break;         // exhausted (absent seg)
        __syncthreads();     // protect s_first/s_last reuse next round
    }

    if (first == INT_MAX || last < 0) return;       // segment absent

    // ---- copy first/last rows (float4; H=1024 -> 1 iter/thread) ----
    const float4* __restrict__ f4 = (const float4*)(x + (size_t)first * H);
    const float4* __restrict__ l4 = (const float4*)(x + (size_t)last  * H);
    float4* __restrict__ o4 = (float4*)(out + (size_t)seg * (2 * H));

    int nvec = H / 4;
    for (int t = tid; t < nvec; t += NTHR) {
        float4 a = __ldg(f4 + t);
        float4 b = __ldg(l4 + t);
        __stcs(o4 + t,        a);   // streaming store: out is write-once
        __stcs(o4 + nvec + t, b);
    }
}

extern "C" void kernel_launch(void* const* d_in, const int* in_sizes, int n_in,
                              void* d_out, int out_size) {
    const float* x    = (const float*)d_in[0];
    const int*   mask = (const int*)d_in[1];
    float*       out  = (float*)d_out;

    int L = in_sizes[1];          // B*S = 32768
    int H = in_sizes[0] / L;      // 1024
    int n = out_size / (2 * H);   // 512

    fused_gather_kernel<<<n, NTHR>>>(x, mask, out, L, H);
}

// round 17
// speedup vs baseline: 1.2609x; 1.2609x over previous
#include <cuda_runtime.h>
#include <cuda_bf16.h>
#include <limits.h>

// FINAL (== best measured R11/R14 form): single self-sufficient kernel.
// Block `seg` finds the first/last occurrence of its own segment id by
// scanning the L2-resident mask (broadcast across all 512 blocks), then
// copies the two rows into the concatenated output. No global scratch, no
// global atomics, no inter-kernel dependency -> trivially graph-replay-safe.
//
// Scan: forward + backward windows processed in the SAME round with all 8
// window loads per thread issued unconditionally (no dependent-load chains),
// block-reduce via shared atomicMin/Max. NOTE: keep the plain while-loop —
// an "early break" after the first barrier measured SLOWER twice (R13, R16);
// the straight-line loop lets ptxas batch the copy loads behind the barrier.
//
// Measured design points (GB300 sm_103a, this bench):
//   - 256 thr/block beats 512 (copy is latency/ramp-bound, not issue-bound)
//   - plain __ldg row loads beat __ldcs; __stcs stores help (write-once out)
//   - fused window-scan beats 2-kernel, PDL-overlap, and grid-barrier forms
//   - wall floor ~6.6 us = ~0.9 replay + ~3.5 ramp/clock floor + ~1.8 work

#define NTHR 256
#define WIN  1024            // ids per window per direction (4 per thread)
#define KPT  (WIN / NTHR)    // 4

__global__ void __launch_bounds__(NTHR) fused_gather_kernel(
        const float* __restrict__ x,
        const int*   __restrict__ mask,
        float*       __restrict__ out,
        int L, int H) {
    const int seg = blockIdx.x;
    const int tid = threadIdx.x;

    __shared__ int s_first, s_last;
    if (tid == 0) { s_first = INT_MAX; s_last = -1; }

    int first = INT_MAX, last = -1;
    int fbase = 0;           // forward window base
    int bend  = L;           // backward window end (exclusive)

    while (first == INT_MAX || last < 0) {
        // ---- batched, unconditional loads for both windows ----
        int fidx[KPT], fval[KPT], bidx[KPT], bval[KPT];
        bool doF = (first == INT_MAX) && (fbase < L);
        bool doB = (last < 0) && (bend > 0);
        int bstart = bend - WIN > 0 ? bend - WIN : 0;
        #pragma unroll
        for (int k = 0; k < KPT; k++) {
            fidx[k] = fbase + tid + k * NTHR;
            bidx[k] = bstart + tid + k * NTHR;
            fval[k] = (doF && fidx[k] < L)    ? __ldg(mask + fidx[k]) : -1;
            bval[k] = (doB && bidx[k] < bend) ? __ldg(mask + bidx[k]) : -1;
        }
        // ---- local reduce, then block reduce via shared atomics ----
        int lf = INT_MAX, lb = -1;
        #pragma unroll
        for (int k = 0; k < KPT; k++) {
            if (fval[k] == seg && fidx[k] < lf) lf = fidx[k];
            if (bval[k] == seg && bidx[k] > lb) lb = bidx[k];
        }
        if (lf != INT_MAX) atomicMin(&s_first, lf);
        if (lb >= 0)       atomicMax(&s_last, lb);
        __syncthreads();
        first = s_first;
        last  = s_last;
        fbase += WIN;
        bend  = bstart;
        if ((first == INT_MAX && fbase >= L) && (last < 0 && bend <= 0)) break;
        __syncthreads();     // protect s_first/s_last reuse next round
    }

    if (first == INT_MAX || last < 0) return;   // segment absent

    // ---- copy first/last rows (float4; H=1024 -> 1 iter/thread) ----
    const float4* __restrict__ f4 = (const float4*)(x + (size_t)first * H);
    const float4* __restrict__ l4 = (const float4*)(x + (size_t)last  * H);
    float4* __restrict__ o4 = (float4*)(out + (size_t)seg * (2 * H));

    int nvec = H / 4;
    for (int t = tid; t < nvec; t += NTHR) {
        float4 a = __ldg(f4 + t);
        float4 b = __ldg(l4 + t);
        __stcs(o4 + t,        a);   // streaming store: out is write-once
        __stcs(o4 + nvec + t, b);
    }
}

extern "C" void kernel_launch(void* const* d_in, const int* in_sizes, int n_in,
                              void* d_out, int out_size) {
    const float* x    = (const float*)d_in[0];
    const int*   mask = (const int*)d_in[1];
    float*       out  = (float*)d_out;

    int L = in_sizes[1];          // B*S = 32768
    int H = in_sizes[0] / L;      // 1024
    int n = out_size / (2 * H);   // 512

    fused_gather_kernel<<<n, NTHR>>>(x, mask, out, L, H);
}